// round 12
// baseline (speedup 1.0000x reference)
#include <cuda_runtime.h>
#include <cuda_bf16.h>
#include <math.h>
#include <stdint.h>

// Problem constants
#define QM 8
#define VV 6890
#define KN 16
#define EE 256
#define HH 8
#define DD 32
#define NTOK (QM * VV)          // 55120
#define FF (4 * EE)             // 1024

// GEMM tiling
#define BM 128
#define BN 128
#define BK 16
#define SKP 24                  // smem row stride in halves (16 + 8 pad; 48B rows)
#define PLANE (BM * SKP)        // halves per plane (3072)
#define STAGE_BYTES (4 * PLANE * 2)   // 24576 B per stage (Ah,Al,Bh,Bl)
#define NSTAGE 3
#define SMEM_BYTES (NSTAGE * STAGE_BYTES)  // 73728 B

// Weight pack offsets (elements) in g_wh / g_wl
#define WOFF_Q  0
#define WOFF_K  65536
#define WOFF_V  131072
#define WOFF_O  196608
#define WOFF_1  262144
#define WOFF_2  524288
#define WTOTAL  786432

// Scratch (static device globals; no runtime allocation)
__device__ float g_qkv[(size_t)NTOK * 768];      // [N][q|k|v] fp32 (attn input)
__device__ float g_x[(size_t)NTOK * EE];         // post-LN1 x fp32 (FFN2 residual)
__device__ __nv_bfloat16 g_mqh[(size_t)NTOK * EE], g_mql[(size_t)NTOK * EE];
__device__ __nv_bfloat16 g_oh [(size_t)NTOK * EE], g_ol [(size_t)NTOK * EE];
__device__ __nv_bfloat16 g_xh [(size_t)NTOK * EE], g_xl [(size_t)NTOK * EE];
__device__ __nv_bfloat16 g_hh [(size_t)NTOK * FF], g_hl [(size_t)NTOK * FF];
__device__ __nv_bfloat16 g_wh[WTOTAL], g_wl[WTOTAL];

// Canonicalized index/mask buffers + dtype flags
__device__ int g_idx64;
__device__ int g_mask32;
__device__ int g_cidx[(size_t)NTOK * KN];
__device__ unsigned char g_cmask[(size_t)NTOK * KN];

// ---------------------------------------------------------------------------
// Dtype detection + canonicalization
// ---------------------------------------------------------------------------
__global__ void detect_kernel(const void* bidx, const void* mask)
{
    __shared__ int s_is64, s_m32;
    if (threadIdx.x == 0) { s_is64 = 1; s_m32 = 1; }
    __syncthreads();

    const unsigned long long* b64 = (const unsigned long long*)bidx;
    for (int i = threadIdx.x; i < 1024; i += blockDim.x)
        if (b64[i] >= (1ull << 32)) atomicExch(&s_is64, 0);

    const unsigned int* m32 = (const unsigned int*)mask;
    for (int i = threadIdx.x; i < 1024; i += blockDim.x)
        if (m32[i] > 1u) atomicExch(&s_m32, 0);

    __syncthreads();
    if (threadIdx.x == 0) { g_idx64 = s_is64; g_mask32 = s_m32; }
}

__global__ void convert_kernel(const void* bidx, const void* graph, const void* mask)
{
    const int is64 = g_idx64;
    const int m32  = g_mask32;
    const int total = NTOK * KN;
    for (int i = blockIdx.x * blockDim.x + threadIdx.x; i < total;
         i += gridDim.x * blockDim.x) {
        int b, g;
        if (is64) {
            b = (int)((const long long*)bidx)[i];
            g = (int)((const long long*)graph)[i];
        } else {
            b = ((const int*)bidx)[i];
            g = ((const int*)graph)[i];
        }
        g_cidx[i] = b * VV + g;
        g_cmask[i] = m32 ? (unsigned char)(((const int*)mask)[i] != 0)
                         : ((const unsigned char*)mask)[i];
    }
}

// ---------------------------------------------------------------------------
// fp32 -> split bf16
// ---------------------------------------------------------------------------
__device__ __forceinline__ void split_bf16(float x, __nv_bfloat16& h, __nv_bfloat16& l) {
    h = __float2bfloat16(x);
    l = __float2bfloat16(x - __bfloat162float(h));
}

struct CvtBatch {
    const float* src[7];
    __nv_bfloat16* H[7];
    __nv_bfloat16* L[7];
    int n[7];
};

__global__ void cvt_split_all(CvtBatch b)
{
    const int seg = blockIdx.y;
    const float* __restrict__ src = b.src[seg];
    __nv_bfloat16* __restrict__ H = b.H[seg];
    __nv_bfloat16* __restrict__ L = b.L[seg];
    const int n = b.n[seg];
    for (int i = (blockIdx.x * blockDim.x + threadIdx.x) * 4; i < n;
         i += gridDim.x * blockDim.x * 4) {
        float4 v = *(const float4*)(src + i);
        __nv_bfloat16 h0, h1, h2, h3, l0, l1, l2, l3;
        split_bf16(v.x, h0, l0); split_bf16(v.y, h1, l1);
        split_bf16(v.z, h2, l2); split_bf16(v.w, h3, l3);
        *(__nv_bfloat162*)(H + i)     = __nv_bfloat162(h0, h1);
        *(__nv_bfloat162*)(H + i + 2) = __nv_bfloat162(h2, h3);
        *(__nv_bfloat162*)(L + i)     = __nv_bfloat162(l0, l1);
        *(__nv_bfloat162*)(L + i + 2) = __nv_bfloat162(l2, l3);
    }
}

// ---------------------------------------------------------------------------
// MMA / async-copy helpers
// ---------------------------------------------------------------------------
__device__ __forceinline__ uint32_t smem_u32(const void* p) {
    return (uint32_t)__cvta_generic_to_shared(p);
}
__device__ __forceinline__ void ldsm_x4(uint32_t& r0, uint32_t& r1,
                                        uint32_t& r2, uint32_t& r3, uint32_t addr) {
    asm volatile("ldmatrix.sync.aligned.m8n8.x4.shared.b16 {%0,%1,%2,%3}, [%4];"
                 : "=r"(r0), "=r"(r1), "=r"(r2), "=r"(r3) : "r"(addr));
}
__device__ __forceinline__ void ldsm_x2(uint32_t& r0, uint32_t& r1, uint32_t addr) {
    asm volatile("ldmatrix.sync.aligned.m8n8.x2.shared.b16 {%0,%1}, [%2];"
                 : "=r"(r0), "=r"(r1) : "r"(addr));
}
__device__ __forceinline__ void mma_bf16(float* d, const uint32_t* a, const uint32_t* b) {
    asm volatile("mma.sync.aligned.m16n8k16.row.col.f32.bf16.bf16.f32 "
                 "{%0,%1,%2,%3}, {%4,%5,%6,%7}, {%8,%9}, {%0,%1,%2,%3};"
                 : "+f"(d[0]), "+f"(d[1]), "+f"(d[2]), "+f"(d[3])
                 : "r"(a[0]), "r"(a[1]), "r"(a[2]), "r"(a[3]), "r"(b[0]), "r"(b[1]));
}
__device__ __forceinline__ void cp_async16(uint32_t dst, const void* src, bool pred) {
    const int sz = pred ? 16 : 0;
    asm volatile("cp.async.cg.shared.global [%0], [%1], 16, %2;"
                 :: "r"(dst), "l"(src), "r"(sz));
}
__device__ __forceinline__ void cp_commit() { asm volatile("cp.async.commit_group;"); }
template<int N>
__device__ __forceinline__ void cp_wait() {
    asm volatile("cp.async.wait_group %0;" :: "n"(N));
}

__device__ __forceinline__ float gelu_exact(float x) {
    return 0.5f * x * (1.0f + erff(x * 0.7071067811865475f));
}

// ---------------------------------------------------------------------------
// Split-bf16 tensor-core GEMM, 3-stage cp.async pipeline (1 barrier/iter),
// dynamic smem, 2 CTAs/SM, A-reuse CTA ordering.
// Grid: (x = ny*nz, y = row blocks). Column block = x % ny, weight z = x / ny.
// ---------------------------------------------------------------------------
template<bool HASRES, bool DOGELU, bool OUTF32, bool OUTBF>
__global__ void __launch_bounds__(256, 2)
gemm_tc(const __nv_bfloat16* __restrict__ Ah, const __nv_bfloat16* __restrict__ Al,
        const __nv_bfloat16* __restrict__ Whb, const __nv_bfloat16* __restrict__ Wlb,
        int wzstride, int ny,
        const float* __restrict__ ba, const float* __restrict__ bb,
        const float* __restrict__ bc,
        float* __restrict__ C, __nv_bfloat16* __restrict__ Ch,
        __nv_bfloat16* __restrict__ Cl,
        const float* __restrict__ res,
        int M, int Kd, int ldc, int zstride)
{
    extern __shared__ __nv_bfloat16 smem[];
    // stage s: Ah at s*4*PLANE, Al +PLANE, Bh +2*PLANE, Bl +3*PLANE

    const int ybk = blockIdx.x % ny;
    const int z   = blockIdx.x / ny;
    const __nv_bfloat16* Wh = Whb + (size_t)z * wzstride;
    const __nv_bfloat16* Wl = Wlb + (size_t)z * wzstride;
    const float* bias = (z == 0) ? ba : (z == 1) ? bb : bc;

    const int tid = threadIdx.x;
    const int lane = tid & 31;
    const int warp = tid >> 5;
    const int wm0 = (warp >> 2) * 64;
    const int wn0 = (warp & 3) * 32;

    const int row0 = blockIdx.y * BM;
    const int wcol0 = ybk * BN;
    const int outbase = z * zstride;

    float acc[4][4][4];
#pragma unroll
    for (int mi = 0; mi < 4; mi++)
#pragma unroll
        for (int ni = 0; ni < 4; ni++)
#pragma unroll
            for (int r = 0; r < 4; r++) acc[mi][ni][r] = 0.0f;

    const int nIter = Kd / BK;

    // Loader: 128 rows x 1 chunk(16B) per plane pair-thread: 256 chunks/plane
    const int lrow = tid >> 1;
    const int lk   = (tid & 1) * 8;          // halves
    const int soff = lrow * SKP + lk;
    const bool ap = (row0 + lrow) < M;

    const uint32_t smem_base = smem_u32(smem);

    // ldmatrix per-thread smem coords
    const int aRow = wm0 + (lane & 15);
    const int aKoff = (lane >> 4) * 8;
    const int bLane = lane & 15;
    const int bRowB = wn0 + (bLane & 7);
    const int bKoff = (bLane >> 3) * 8;

    // ---- preload stages 0,1 ----
#pragma unroll
    for (int s = 0; s < 2; s++) {
        if (s < nIter) {
            const int kb = s * BK;
            const uint32_t st = smem_base + s * STAGE_BYTES;
            const size_t aoff = (size_t)(row0 + lrow) * Kd + kb + lk;
            const size_t boff = (size_t)(wcol0 + lrow) * Kd + kb + lk;
            cp_async16(st + soff * 2,                 Ah + aoff, ap);
            cp_async16(st + (PLANE + soff) * 2,       Al + aoff, ap);
            cp_async16(st + (2 * PLANE + soff) * 2,   Wh + boff, true);
            cp_async16(st + (3 * PLANE + soff) * 2,   Wl + boff, true);
        }
        cp_commit();
    }

    int cur = 0;
    for (int it = 0; it < nIter; it++) {
        if (it + 1 < nIter) cp_wait<1>(); else cp_wait<0>();
        __syncthreads();   // stage cur ready; compute(it-1) done on all threads

        // load stage (it+2)%3 (the one freed by compute(it-1))
        if (it + 2 < nIter) {
            int ns = cur + 2; if (ns >= NSTAGE) ns -= NSTAGE;
            const int kb = (it + 2) * BK;
            const uint32_t st = smem_base + ns * STAGE_BYTES;
            const size_t aoff = (size_t)(row0 + lrow) * Kd + kb + lk;
            const size_t boff = (size_t)(wcol0 + lrow) * Kd + kb + lk;
            cp_async16(st + soff * 2,                 Ah + aoff, ap);
            cp_async16(st + (PLANE + soff) * 2,       Al + aoff, ap);
            cp_async16(st + (2 * PLANE + soff) * 2,   Wh + boff, true);
            cp_async16(st + (3 * PLANE + soff) * 2,   Wl + boff, true);
            cp_commit();
        }

        // ---- compute one 16-k step on stage cur ----
        const uint32_t st = smem_base + cur * STAGE_BYTES;
        uint32_t ahf[4][4], alf[4][4], bhf[4][2], blf[4][2];
#pragma unroll
        for (int mi = 0; mi < 4; mi++) {
            const int off = ((aRow + mi * 16) * SKP + aKoff) * 2;
            ldsm_x4(ahf[mi][0], ahf[mi][1], ahf[mi][2], ahf[mi][3], st + off);
            ldsm_x4(alf[mi][0], alf[mi][1], alf[mi][2], alf[mi][3],
                    st + PLANE * 2 + off);
        }
#pragma unroll
        for (int ni = 0; ni < 4; ni++) {
            const int off = ((bRowB + ni * 8) * SKP + bKoff) * 2;
            ldsm_x2(bhf[ni][0], bhf[ni][1], st + 2 * PLANE * 2 + off);
            ldsm_x2(blf[ni][0], blf[ni][1], st + 3 * PLANE * 2 + off);
        }
#pragma unroll
        for (int mi = 0; mi < 4; mi++)
#pragma unroll
            for (int ni = 0; ni < 4; ni++) {
                mma_bf16(acc[mi][ni], ahf[mi], bhf[ni]);
                mma_bf16(acc[mi][ni], ahf[mi], blf[ni]);
                mma_bf16(acc[mi][ni], alf[mi], bhf[ni]);
            }

        cur++; if (cur >= NSTAGE) cur = 0;
    }

    // ---- epilogue ----
#pragma unroll
    for (int mi = 0; mi < 4; mi++) {
#pragma unroll
        for (int ni = 0; ni < 4; ni++) {
            const int rA = row0 + wm0 + mi * 16 + (lane >> 2);
            const int cw = wcol0 + wn0 + ni * 8 + 2 * (lane & 3);  // bias index
            const int cg = outbase + cw;                           // output col
            const float b0 = bias[cw], b1 = bias[cw + 1];
#pragma unroll
            for (int half = 0; half < 2; half++) {
                const int r = rA + half * 8;
                if (r >= M) continue;
                float v0 = acc[mi][ni][half * 2 + 0] + b0;
                float v1 = acc[mi][ni][half * 2 + 1] + b1;
                if (HASRES) {
                    v0 += res[(size_t)r * ldc + cg];
                    v1 += res[(size_t)r * ldc + cg + 1];
                }
                if (DOGELU) { v0 = gelu_exact(v0); v1 = gelu_exact(v1); }
                if (OUTF32)
                    *(float2*)(C + (size_t)r * ldc + cg) = make_float2(v0, v1);
                if (OUTBF) {
                    __nv_bfloat16 h0, h1, l0, l1;
                    split_bf16(v0, h0, l0); split_bf16(v1, h1, l1);
                    *(__nv_bfloat162*)(Ch + (size_t)r * ldc + cg) = __nv_bfloat162(h0, h1);
                    *(__nv_bfloat162*)(Cl + (size_t)r * ldc + cg) = __nv_bfloat162(l0, l1);
                }
            }
        }
    }
}

// ---------------------------------------------------------------------------
// Attention: one block per token (8 warps = 8 heads); writes split-bf16 o.
// ---------------------------------------------------------------------------
__global__ void __launch_bounds__(256)
attn_kernel(const float* __restrict__ qkv,
            __nv_bfloat16* __restrict__ oh, __nv_bfloat16* __restrict__ ol)
{
    const int n = blockIdx.x;
    __shared__ int s_m[KN];
    __shared__ unsigned char s_mask[KN];

    const int tid = threadIdx.x;
    if (tid < KN) {
        s_m[tid] = g_cidx[(size_t)n * KN + tid];
        s_mask[tid] = g_cmask[(size_t)n * KN + tid];
    }
    __syncthreads();

    const int h = tid >> 5;
    const int lane = tid & 31;
    const int hofs = h * DD + lane;

    const float qv = qkv[(size_t)n * 768 + hofs];

    float sc[KN];
#pragma unroll
    for (int k = 0; k < KN; k++) {
        float p = qv * qkv[(size_t)s_m[k] * 768 + 256 + hofs];
        p += __shfl_xor_sync(0xffffffffu, p, 16);
        p += __shfl_xor_sync(0xffffffffu, p, 8);
        p += __shfl_xor_sync(0xffffffffu, p, 4);
        p += __shfl_xor_sync(0xffffffffu, p, 2);
        p += __shfl_xor_sync(0xffffffffu, p, 1);
        sc[k] = p;
    }

    const float NEGINF = __int_as_float(0xff800000);
    float mx = NEGINF;
#pragma unroll
    for (int k = 0; k < KN; k++) {
        sc[k] = s_mask[k] ? NEGINF : sc[k] * 0.1767766952966369f;
        mx = fmaxf(mx, sc[k]);
    }
    float sum = 0.0f;
#pragma unroll
    for (int k = 0; k < KN; k++) {
        sc[k] = __expf(sc[k] - mx);
        sum += sc[k];
    }
    const float inv = 1.0f / sum;

    float accv = 0.0f;
#pragma unroll
    for (int k = 0; k < KN; k++)
        accv = fmaf(sc[k], qkv[(size_t)s_m[k] * 768 + 512 + hofs], accv);

    const float v = accv * inv;
    __nv_bfloat16 hh, ll;
    split_bf16(v, hh, ll);
    oh[(size_t)n * EE + hofs] = hh;
    ol[(size_t)n * EE + hofs] = ll;
}

// ---------------------------------------------------------------------------
// LayerNorm over E=256, warp per row, in-place fp32; optional split-bf16 out.
// ---------------------------------------------------------------------------
template<bool WRITEBF>
__global__ void __launch_bounds__(256)
ln_kernel(float* __restrict__ X, const float* __restrict__ gamma,
          const float* __restrict__ beta,
          __nv_bfloat16* __restrict__ Xh, __nv_bfloat16* __restrict__ Xl, int rows)
{
    const int row = blockIdx.x * 8 + (threadIdx.x >> 5);
    if (row >= rows) return;
    const int lane = threadIdx.x & 31;
    float* xr = X + (size_t)row * EE;

    float v[8];
    float s = 0.0f;
#pragma unroll
    for (int i = 0; i < 8; i++) {
        v[i] = xr[lane + i * 32];
        s += v[i];
    }
#pragma unroll
    for (int d = 16; d > 0; d >>= 1) s += __shfl_xor_sync(0xffffffffu, s, d);
    const float mean = s * (1.0f / 256.0f);

    float var = 0.0f;
#pragma unroll
    for (int i = 0; i < 8; i++) {
        const float d = v[i] - mean;
        var = fmaf(d, d, var);
    }
#pragma unroll
    for (int d = 16; d > 0; d >>= 1) var += __shfl_xor_sync(0xffffffffu, var, d);
    const float rstd = rsqrtf(var * (1.0f / 256.0f) + 1e-5f);

#pragma unroll
    for (int i = 0; i < 8; i++) {
        const int c = lane + i * 32;
        const float y = (v[i] - mean) * rstd * gamma[c] + beta[c];
        xr[c] = y;
        if (WRITEBF) {
            __nv_bfloat16 h, l;
            split_bf16(y, h, l);
            Xh[(size_t)row * EE + c] = h;
            Xl[(size_t)row * EE + c] = l;
        }
    }
}

// ---------------------------------------------------------------------------
extern "C" void kernel_launch(void* const* d_in, const int* in_sizes, int n_in,
                              void* d_out, int out_size)
{
    const float* mq    = (const float*)d_in[0];
    const float* Wq    = (const float*)d_in[1];
    const float* bq    = (const float*)d_in[2];
    const float* Wk    = (const float*)d_in[3];
    const float* bk    = (const float*)d_in[4];
    const float* Wv    = (const float*)d_in[5];
    const float* bv    = (const float*)d_in[6];
    const float* Wo    = (const float*)d_in[7];
    const float* bo    = (const float*)d_in[8];
    const float* ln1g  = (const float*)d_in[9];
    const float* ln1b  = (const float*)d_in[10];
    const float* W1    = (const float*)d_in[11];
    const float* b1    = (const float*)d_in[12];
    const float* W2    = (const float*)d_in[13];
    const float* b2    = (const float*)d_in[14];
    const float* ln2g  = (const float*)d_in[15];
    const float* ln2b  = (const float*)d_in[16];
    const void*  bidx  = d_in[17];
    const void*  graph = d_in[18];
    const void*  mask  = d_in[19];

    float* out = (float*)d_out;

    float* qkv; cudaGetSymbolAddress((void**)&qkv, g_qkv);
    float* x;   cudaGetSymbolAddress((void**)&x,   g_x);
    __nv_bfloat16 *mqh, *mql, *oh, *ol, *xh, *xl, *hh, *hl, *wh, *wl;
    cudaGetSymbolAddress((void**)&mqh, g_mqh);
    cudaGetSymbolAddress((void**)&mql, g_mql);
    cudaGetSymbolAddress((void**)&oh,  g_oh);
    cudaGetSymbolAddress((void**)&ol,  g_ol);
    cudaGetSymbolAddress((void**)&xh,  g_xh);
    cudaGetSymbolAddress((void**)&xl,  g_xl);
    cudaGetSymbolAddress((void**)&hh,  g_hh);
    cudaGetSymbolAddress((void**)&hl,  g_hl);
    cudaGetSymbolAddress((void**)&wh,  g_wh);
    cudaGetSymbolAddress((void**)&wl,  g_wl);

    // Allow 72 KB dynamic smem for all gemm_tc instantiations
    cudaFuncSetAttribute(gemm_tc<false, false, true,  false>,
                         cudaFuncAttributeMaxDynamicSharedMemorySize, SMEM_BYTES);
    cudaFuncSetAttribute(gemm_tc<true,  false, true,  false>,
                         cudaFuncAttributeMaxDynamicSharedMemorySize, SMEM_BYTES);
    cudaFuncSetAttribute(gemm_tc<false, true,  false, true>,
                         cudaFuncAttributeMaxDynamicSharedMemorySize, SMEM_BYTES);

    const int M = NTOK;
    const int MB = (M + BM - 1) / BM;   // 431

    // 0) Index/mask canonicalization
    detect_kernel<<<1, 256>>>(bidx, mask);
    convert_kernel<<<256, 256>>>(bidx, graph, mask);

    // 0b) One batched split-bf16 conversion (mq + 6 weights)
    {
        CvtBatch b;
        b.src[0] = mq; b.H[0] = mqh;          b.L[0] = mql;          b.n[0] = NTOK * EE;
        b.src[1] = Wq; b.H[1] = wh + WOFF_Q;  b.L[1] = wl + WOFF_Q;  b.n[1] = EE * EE;
        b.src[2] = Wk; b.H[2] = wh + WOFF_K;  b.L[2] = wl + WOFF_K;  b.n[2] = EE * EE;
        b.src[3] = Wv; b.H[3] = wh + WOFF_V;  b.L[3] = wl + WOFF_V;  b.n[3] = EE * EE;
        b.src[4] = Wo; b.H[4] = wh + WOFF_O;  b.L[4] = wl + WOFF_O;  b.n[4] = EE * EE;
        b.src[5] = W1; b.H[5] = wh + WOFF_1;  b.L[5] = wl + WOFF_1;  b.n[5] = FF * EE;
        b.src[6] = W2; b.H[6] = wh + WOFF_2;  b.L[6] = wl + WOFF_2;  b.n[6] = EE * FF;
        dim3 grid(128, 7);
        cvt_split_all<<<grid, 256>>>(b);
    }

    // 1) Fused Q/K/V projections -> qkv fp32 (x = 2 cols * 3 weights, y = rows)
    {
        dim3 grid(6, MB);
        gemm_tc<false, false, true, false><<<grid, 256, SMEM_BYTES>>>(
            mqh, mql, wh, wl, 65536, 2, bq, bk, bv,
            qkv, nullptr, nullptr, nullptr, M, EE, 768, 256);
    }

    // 2) Attention -> split-bf16 o
    attn_kernel<<<M, 256>>>(qkv, oh, ol);

    // 3) Wo projection + residual(mq) -> x fp32; LN1 + split-bf16 x
    {
        dim3 grid(2, MB);
        gemm_tc<true, false, true, false><<<grid, 256, SMEM_BYTES>>>(
            oh, ol, wh + WOFF_O, wl + WOFF_O, 0, 2, bo, bo, bo,
            x, nullptr, nullptr, mq, M, EE, EE, 0);
        ln_kernel<true><<<(M + 7) / 8, 256>>>(x, ln1g, ln1b, xh, xl, M);
    }

    // 4) FFN1 + GELU -> split-bf16 h only
    {
        dim3 grid(8, MB);
        gemm_tc<false, true, false, true><<<grid, 256, SMEM_BYTES>>>(
            xh, xl, wh + WOFF_1, wl + WOFF_1, 0, 8, b1, b1, b1,
            nullptr, hh, hl, nullptr, M, EE, FF, 0);
    }

    // 5) FFN2 + residual(x) -> out fp32; LN2 in-place
    {
        dim3 grid(2, MB);
        gemm_tc<true, false, true, false><<<grid, 256, SMEM_BYTES>>>(
            hh, hl, wh + WOFF_2, wl + WOFF_2, 0, 2, b2, b2, b2,
            out, nullptr, nullptr, x, M, FF, EE, 0);
        ln_kernel<false><<<(M + 7) / 8, 256>>>(out, ln2g, ln2b, nullptr, nullptr, M);
    }
}

// round 14
// speedup vs baseline: 1.0317x; 1.0317x over previous
#include <cuda_runtime.h>
#include <cuda_bf16.h>
#include <math.h>
#include <stdint.h>

// Problem constants
#define QM 8
#define VV 6890
#define KN 16
#define EE 256
#define HH 8
#define DD 32
#define NTOK (QM * VV)          // 55120
#define FF (4 * EE)             // 1024

// GEMM tiling (R10-proven 3-stage BK16 pipeline)
#define BM 128
#define BN 128
#define BK 16
#define SKP 24                  // smem row stride in halves (16 + 8 pad; 48B rows)
#define PLANE (BM * SKP)        // halves per plane (3072)
#define STAGE_BYTES (4 * PLANE * 2)   // 24576 B per stage (Ah,Al,Bh,Bl)
#define NSTAGE 3
#define SMEM_BYTES (NSTAGE * STAGE_BYTES)  // 73728 B

// Weight pack offsets (elements) in g_wh / g_wl
#define WOFF_Q  0
#define WOFF_K  65536
#define WOFF_V  131072
#define WOFF_O  196608
#define WOFF_1  262144
#define WOFF_2  524288
#define WTOTAL  786432

// Scratch (static device globals; no runtime allocation)
__device__ float g_q[(size_t)NTOK * EE];          // fp32 Q (attn input)
__device__ __nv_bfloat16 g_kv[(size_t)NTOK * 512]; // bf16 K|V (attn gather)
__device__ float g_x[(size_t)NTOK * EE];          // post-LN1 x fp32
__device__ __nv_bfloat16 g_mqh[(size_t)NTOK * EE], g_mql[(size_t)NTOK * EE];
__device__ __nv_bfloat16 g_oh [(size_t)NTOK * EE], g_ol [(size_t)NTOK * EE];
__device__ __nv_bfloat16 g_xh [(size_t)NTOK * EE], g_xl [(size_t)NTOK * EE];
__device__ __nv_bfloat16 g_hh [(size_t)NTOK * FF], g_hl [(size_t)NTOK * FF];
__device__ __nv_bfloat16 g_wh[WTOTAL], g_wl[WTOTAL];

__device__ int g_idx64;
__device__ int g_mask32;
__device__ int g_cidx[(size_t)NTOK * KN];
__device__ unsigned char g_cmask[(size_t)NTOK * KN];

// ---------------------------------------------------------------------------
// Dtype detection + canonicalization
// ---------------------------------------------------------------------------
__global__ void detect_kernel(const void* bidx, const void* mask)
{
    __shared__ int s_is64, s_m32;
    if (threadIdx.x == 0) { s_is64 = 1; s_m32 = 1; }
    __syncthreads();

    const unsigned long long* b64 = (const unsigned long long*)bidx;
    for (int i = threadIdx.x; i < 1024; i += blockDim.x)
        if (b64[i] >= (1ull << 32)) atomicExch(&s_is64, 0);

    const unsigned int* m32 = (const unsigned int*)mask;
    for (int i = threadIdx.x; i < 1024; i += blockDim.x)
        if (m32[i] > 1u) atomicExch(&s_m32, 0);

    __syncthreads();
    if (threadIdx.x == 0) { g_idx64 = s_is64; g_mask32 = s_m32; }
}

__global__ void convert_kernel(const void* bidx, const void* graph, const void* mask)
{
    const int is64 = g_idx64;
    const int m32  = g_mask32;
    const int total = NTOK * KN;
    for (int i = blockIdx.x * blockDim.x + threadIdx.x; i < total;
         i += gridDim.x * blockDim.x) {
        int b, g;
        if (is64) {
            b = (int)((const long long*)bidx)[i];
            g = (int)((const long long*)graph)[i];
        } else {
            b = ((const int*)bidx)[i];
            g = ((const int*)graph)[i];
        }
        g_cidx[i] = b * VV + g;
        g_cmask[i] = m32 ? (unsigned char)(((const int*)mask)[i] != 0)
                         : ((const unsigned char*)mask)[i];
    }
}

// ---------------------------------------------------------------------------
// fp32 -> split bf16
// ---------------------------------------------------------------------------
__device__ __forceinline__ void split_bf16(float x, __nv_bfloat16& h, __nv_bfloat16& l) {
    h = __float2bfloat16(x);
    l = __float2bfloat16(x - __bfloat162float(h));
}

struct CvtBatch {
    const float* src[7];
    __nv_bfloat16* H[7];
    __nv_bfloat16* L[7];
    int n[7];
};

__global__ void cvt_split_all(CvtBatch b)
{
    const int seg = blockIdx.y;
    const float* __restrict__ src = b.src[seg];
    __nv_bfloat16* __restrict__ H = b.H[seg];
    __nv_bfloat16* __restrict__ L = b.L[seg];
    const int n = b.n[seg];
    for (int i = (blockIdx.x * blockDim.x + threadIdx.x) * 4; i < n;
         i += gridDim.x * blockDim.x * 4) {
        float4 v = *(const float4*)(src + i);
        __nv_bfloat16 h0, h1, h2, h3, l0, l1, l2, l3;
        split_bf16(v.x, h0, l0); split_bf16(v.y, h1, l1);
        split_bf16(v.z, h2, l2); split_bf16(v.w, h3, l3);
        *(__nv_bfloat162*)(H + i)     = __nv_bfloat162(h0, h1);
        *(__nv_bfloat162*)(H + i + 2) = __nv_bfloat162(h2, h3);
        *(__nv_bfloat162*)(L + i)     = __nv_bfloat162(l0, l1);
        *(__nv_bfloat162*)(L + i + 2) = __nv_bfloat162(l2, l3);
    }
}

// ---------------------------------------------------------------------------
// MMA / async-copy helpers
// ---------------------------------------------------------------------------
__device__ __forceinline__ uint32_t smem_u32(const void* p) {
    return (uint32_t)__cvta_generic_to_shared(p);
}
__device__ __forceinline__ void ldsm_x4(uint32_t& r0, uint32_t& r1,
                                        uint32_t& r2, uint32_t& r3, uint32_t addr) {
    asm volatile("ldmatrix.sync.aligned.m8n8.x4.shared.b16 {%0,%1,%2,%3}, [%4];"
                 : "=r"(r0), "=r"(r1), "=r"(r2), "=r"(r3) : "r"(addr));
}
__device__ __forceinline__ void ldsm_x2(uint32_t& r0, uint32_t& r1, uint32_t addr) {
    asm volatile("ldmatrix.sync.aligned.m8n8.x2.shared.b16 {%0,%1}, [%2];"
                 : "=r"(r0), "=r"(r1) : "r"(addr));
}
__device__ __forceinline__ void mma_bf16(float* d, const uint32_t* a, const uint32_t* b) {
    asm volatile("mma.sync.aligned.m16n8k16.row.col.f32.bf16.bf16.f32 "
                 "{%0,%1,%2,%3}, {%4,%5,%6,%7}, {%8,%9}, {%0,%1,%2,%3};"
                 : "+f"(d[0]), "+f"(d[1]), "+f"(d[2]), "+f"(d[3])
                 : "r"(a[0]), "r"(a[1]), "r"(a[2]), "r"(a[3]), "r"(b[0]), "r"(b[1]));
}
__device__ __forceinline__ void cp_async16(uint32_t dst, const void* src, bool pred) {
    const int sz = pred ? 16 : 0;
    asm volatile("cp.async.cg.shared.global [%0], [%1], 16, %2;"
                 :: "r"(dst), "l"(src), "r"(sz));
}
__device__ __forceinline__ void cp_commit() { asm volatile("cp.async.commit_group;"); }
template<int N>
__device__ __forceinline__ void cp_wait() {
    asm volatile("cp.async.wait_group %0;" :: "n"(N));
}

__device__ __forceinline__ float gelu_exact(float x) {
    return 0.5f * x * (1.0f + erff(x * 0.7071067811865475f));
}

// ---------------------------------------------------------------------------
// Split-bf16 tensor-core GEMM, 3-stage cp.async pipeline (R10 config).
// Outputs: fp32 C (OUTF32), split-bf16 Ch/Cl (OUTBF), or QKV mode (OUTKV):
//   z==0 -> fp32 C (ldc), z==1/2 -> single bf16 into Ckv[N][512] at (z-1)*256.
// ---------------------------------------------------------------------------
template<bool HASRES, bool DOGELU, bool OUTF32, bool OUTBF, bool OUTKV>
__global__ void __launch_bounds__(256, 2)
gemm_tc(const __nv_bfloat16* __restrict__ Ah, const __nv_bfloat16* __restrict__ Al,
        const __nv_bfloat16* __restrict__ Whb, const __nv_bfloat16* __restrict__ Wlb,
        int wzstride,
        const float* __restrict__ ba, const float* __restrict__ bb,
        const float* __restrict__ bc,
        float* __restrict__ C, __nv_bfloat16* __restrict__ Ch,
        __nv_bfloat16* __restrict__ Cl, __nv_bfloat16* __restrict__ Ckv,
        const float* __restrict__ res,
        int M, int Kd, int ldc)
{
    extern __shared__ __nv_bfloat16 smem[];

    const int z = blockIdx.z;
    const __nv_bfloat16* Wh = Whb + (size_t)z * wzstride;
    const __nv_bfloat16* Wl = Wlb + (size_t)z * wzstride;
    const float* bias = (z == 0) ? ba : (z == 1) ? bb : bc;

    const int tid = threadIdx.x;
    const int lane = tid & 31;
    const int warp = tid >> 5;
    const int wm0 = (warp >> 2) * 64;
    const int wn0 = (warp & 3) * 32;

    const int row0 = blockIdx.x * BM;
    const int wcol0 = blockIdx.y * BN;

    float acc[4][4][4];
#pragma unroll
    for (int mi = 0; mi < 4; mi++)
#pragma unroll
        for (int ni = 0; ni < 4; ni++)
#pragma unroll
            for (int r = 0; r < 4; r++) acc[mi][ni][r] = 0.0f;

    const int nIter = Kd / BK;

    const int lrow = tid >> 1;
    const int lk   = (tid & 1) * 8;
    const int soff = lrow * SKP + lk;
    const bool ap = (row0 + lrow) < M;

    const uint32_t smem_base = smem_u32(smem);

    const int aRow = wm0 + (lane & 15);
    const int aKoff = (lane >> 4) * 8;
    const int bLane = lane & 15;
    const int bRowB = wn0 + (bLane & 7);
    const int bKoff = (bLane >> 3) * 8;

    // ---- preload stages 0,1 ----
#pragma unroll
    for (int s = 0; s < 2; s++) {
        if (s < nIter) {
            const int kb = s * BK;
            const uint32_t st = smem_base + s * STAGE_BYTES;
            const size_t aoff = (size_t)(row0 + lrow) * Kd + kb + lk;
            const size_t boff = (size_t)(wcol0 + lrow) * Kd + kb + lk;
            cp_async16(st + soff * 2,                 Ah + aoff, ap);
            cp_async16(st + (PLANE + soff) * 2,       Al + aoff, ap);
            cp_async16(st + (2 * PLANE + soff) * 2,   Wh + boff, true);
            cp_async16(st + (3 * PLANE + soff) * 2,   Wl + boff, true);
        }
        cp_commit();
    }

    int cur = 0;
    for (int it = 0; it < nIter; it++) {
        if (it + 1 < nIter) cp_wait<1>(); else cp_wait<0>();
        __syncthreads();

        if (it + 2 < nIter) {
            int ns = cur + 2; if (ns >= NSTAGE) ns -= NSTAGE;
            const int kb = (it + 2) * BK;
            const uint32_t st = smem_base + ns * STAGE_BYTES;
            const size_t aoff = (size_t)(row0 + lrow) * Kd + kb + lk;
            const size_t boff = (size_t)(wcol0 + lrow) * Kd + kb + lk;
            cp_async16(st + soff * 2,                 Ah + aoff, ap);
            cp_async16(st + (PLANE + soff) * 2,       Al + aoff, ap);
            cp_async16(st + (2 * PLANE + soff) * 2,   Wh + boff, true);
            cp_async16(st + (3 * PLANE + soff) * 2,   Wl + boff, true);
            cp_commit();
        }

        const uint32_t st = smem_base + cur * STAGE_BYTES;
        uint32_t ahf[4][4], alf[4][4], bhf[4][2], blf[4][2];
#pragma unroll
        for (int mi = 0; mi < 4; mi++) {
            const int off = ((aRow + mi * 16) * SKP + aKoff) * 2;
            ldsm_x4(ahf[mi][0], ahf[mi][1], ahf[mi][2], ahf[mi][3], st + off);
            ldsm_x4(alf[mi][0], alf[mi][1], alf[mi][2], alf[mi][3],
                    st + PLANE * 2 + off);
        }
#pragma unroll
        for (int ni = 0; ni < 4; ni++) {
            const int off = ((bRowB + ni * 8) * SKP + bKoff) * 2;
            ldsm_x2(bhf[ni][0], bhf[ni][1], st + 2 * PLANE * 2 + off);
            ldsm_x2(blf[ni][0], blf[ni][1], st + 3 * PLANE * 2 + off);
        }
#pragma unroll
        for (int mi = 0; mi < 4; mi++)
#pragma unroll
            for (int ni = 0; ni < 4; ni++) {
                mma_bf16(acc[mi][ni], ahf[mi], bhf[ni]);
                mma_bf16(acc[mi][ni], ahf[mi], blf[ni]);
                mma_bf16(acc[mi][ni], alf[mi], bhf[ni]);
            }

        cur++; if (cur >= NSTAGE) cur = 0;
    }

    // ---- epilogue ----
#pragma unroll
    for (int mi = 0; mi < 4; mi++) {
#pragma unroll
        for (int ni = 0; ni < 4; ni++) {
            const int rA = row0 + wm0 + mi * 16 + (lane >> 2);
            const int cw = wcol0 + wn0 + ni * 8 + 2 * (lane & 3);  // weight col
            const float b0 = bias[cw], b1 = bias[cw + 1];
#pragma unroll
            for (int half = 0; half < 2; half++) {
                const int r = rA + half * 8;
                if (r >= M) continue;
                float v0 = acc[mi][ni][half * 2 + 0] + b0;
                float v1 = acc[mi][ni][half * 2 + 1] + b1;
                if (HASRES) {
                    v0 += res[(size_t)r * ldc + cw];
                    v1 += res[(size_t)r * ldc + cw + 1];
                }
                if (DOGELU) { v0 = gelu_exact(v0); v1 = gelu_exact(v1); }
                if (OUTKV) {
                    if (z == 0) {
                        *(float2*)(C + (size_t)r * ldc + cw) = make_float2(v0, v1);
                    } else {
                        const int kcol = (z - 1) * 256 + cw;
                        *(__nv_bfloat162*)(Ckv + (size_t)r * 512 + kcol) =
                            __nv_bfloat162(__float2bfloat16(v0), __float2bfloat16(v1));
                    }
                } else {
                    if (OUTF32)
                        *(float2*)(C + (size_t)r * ldc + cw) = make_float2(v0, v1);
                    if (OUTBF) {
                        __nv_bfloat16 h0, h1, l0, l1;
                        split_bf16(v0, h0, l0); split_bf16(v1, h1, l1);
                        *(__nv_bfloat162*)(Ch + (size_t)r * ldc + cw) = __nv_bfloat162(h0, h1);
                        *(__nv_bfloat162*)(Cl + (size_t)r * ldc + cw) = __nv_bfloat162(l0, l1);
                    }
                }
            }
        }
    }
}

// ---------------------------------------------------------------------------
// Attention: one block per token (8 warps = 8 heads). Q fp32, K/V bf16 gather.
// ---------------------------------------------------------------------------
__global__ void __launch_bounds__(256)
attn_kernel(const float* __restrict__ q, const __nv_bfloat16* __restrict__ kv,
            __nv_bfloat16* __restrict__ oh, __nv_bfloat16* __restrict__ ol)
{
    const int n = blockIdx.x;
    __shared__ int s_m[KN];
    __shared__ unsigned char s_mask[KN];

    const int tid = threadIdx.x;
    if (tid < KN) {
        s_m[tid] = g_cidx[(size_t)n * KN + tid];
        s_mask[tid] = g_cmask[(size_t)n * KN + tid];
    }
    __syncthreads();

    const int h = tid >> 5;
    const int lane = tid & 31;
    const int hofs = h * DD + lane;

    const float qv = q[(size_t)n * EE + hofs];

    float sc[KN];
#pragma unroll
    for (int k = 0; k < KN; k++) {
        float p = qv * __bfloat162float(kv[(size_t)s_m[k] * 512 + hofs]);
        p += __shfl_xor_sync(0xffffffffu, p, 16);
        p += __shfl_xor_sync(0xffffffffu, p, 8);
        p += __shfl_xor_sync(0xffffffffu, p, 4);
        p += __shfl_xor_sync(0xffffffffu, p, 2);
        p += __shfl_xor_sync(0xffffffffu, p, 1);
        sc[k] = p;
    }

    const float NEGINF = __int_as_float(0xff800000);
    float mx = NEGINF;
#pragma unroll
    for (int k = 0; k < KN; k++) {
        sc[k] = s_mask[k] ? NEGINF : sc[k] * 0.1767766952966369f;
        mx = fmaxf(mx, sc[k]);
    }
    float sum = 0.0f;
#pragma unroll
    for (int k = 0; k < KN; k++) {
        sc[k] = __expf(sc[k] - mx);
        sum += sc[k];
    }
    const float inv = 1.0f / sum;

    float accv = 0.0f;
#pragma unroll
    for (int k = 0; k < KN; k++)
        accv = fmaf(sc[k], __bfloat162float(kv[(size_t)s_m[k] * 512 + 256 + hofs]),
                    accv);

    const float v = accv * inv;
    __nv_bfloat16 hh, ll;
    split_bf16(v, hh, ll);
    oh[(size_t)n * EE + hofs] = hh;
    ol[(size_t)n * EE + hofs] = ll;
}

// ---------------------------------------------------------------------------
// LayerNorm over E=256, warp per row, in-place fp32; optional split-bf16 out.
// ---------------------------------------------------------------------------
template<bool WRITEBF>
__global__ void __launch_bounds__(256)
ln_kernel(float* __restrict__ X, const float* __restrict__ gamma,
          const float* __restrict__ beta,
          __nv_bfloat16* __restrict__ Xh, __nv_bfloat16* __restrict__ Xl, int rows)
{
    const int row = blockIdx.x * 8 + (threadIdx.x >> 5);
    if (row >= rows) return;
    const int lane = threadIdx.x & 31;
    float* xr = X + (size_t)row * EE;

    float v[8];
    float s = 0.0f;
#pragma unroll
    for (int i = 0; i < 8; i++) {
        v[i] = xr[lane + i * 32];
        s += v[i];
    }
#pragma unroll
    for (int d = 16; d > 0; d >>= 1) s += __shfl_xor_sync(0xffffffffu, s, d);
    const float mean = s * (1.0f / 256.0f);

    float var = 0.0f;
#pragma unroll
    for (int i = 0; i < 8; i++) {
        const float d = v[i] - mean;
        var = fmaf(d, d, var);
    }
#pragma unroll
    for (int d = 16; d > 0; d >>= 1) var += __shfl_xor_sync(0xffffffffu, var, d);
    const float rstd = rsqrtf(var * (1.0f / 256.0f) + 1e-5f);

#pragma unroll
    for (int i = 0; i < 8; i++) {
        const int c = lane + i * 32;
        const float y = (v[i] - mean) * rstd * gamma[c] + beta[c];
        xr[c] = y;
        if (WRITEBF) {
            __nv_bfloat16 h, l;
            split_bf16(y, h, l);
            Xh[(size_t)row * EE + c] = h;
            Xl[(size_t)row * EE + c] = l;
        }
    }
}

// ---------------------------------------------------------------------------
extern "C" void kernel_launch(void* const* d_in, const int* in_sizes, int n_in,
                              void* d_out, int out_size)
{
    const float* mq    = (const float*)d_in[0];
    const float* Wq    = (const float*)d_in[1];
    const float* bq    = (const float*)d_in[2];
    const float* Wk    = (const float*)d_in[3];
    const float* bk    = (const float*)d_in[4];
    const float* Wv    = (const float*)d_in[5];
    const float* bv    = (const float*)d_in[6];
    const float* Wo    = (const float*)d_in[7];
    const float* bo    = (const float*)d_in[8];
    const float* ln1g  = (const float*)d_in[9];
    const float* ln1b  = (const float*)d_in[10];
    const float* W1    = (const float*)d_in[11];
    const float* b1    = (const float*)d_in[12];
    const float* W2    = (const float*)d_in[13];
    const float* b2    = (const float*)d_in[14];
    const float* ln2g  = (const float*)d_in[15];
    const float* ln2b  = (const float*)d_in[16];
    const void*  bidx  = d_in[17];
    const void*  graph = d_in[18];
    const void*  mask  = d_in[19];

    float* out = (float*)d_out;

    float* q;   cudaGetSymbolAddress((void**)&q,   g_q);
    float* x;   cudaGetSymbolAddress((void**)&x,   g_x);
    __nv_bfloat16 *kvb, *mqh, *mql, *oh, *ol, *xh, *xl, *hh, *hl, *wh, *wl;
    cudaGetSymbolAddress((void**)&kvb, g_kv);
    cudaGetSymbolAddress((void**)&mqh, g_mqh);
    cudaGetSymbolAddress((void**)&mql, g_mql);
    cudaGetSymbolAddress((void**)&oh,  g_oh);
    cudaGetSymbolAddress((void**)&ol,  g_ol);
    cudaGetSymbolAddress((void**)&xh,  g_xh);
    cudaGetSymbolAddress((void**)&xl,  g_xl);
    cudaGetSymbolAddress((void**)&hh,  g_hh);
    cudaGetSymbolAddress((void**)&hl,  g_hl);
    cudaGetSymbolAddress((void**)&wh,  g_wh);
    cudaGetSymbolAddress((void**)&wl,  g_wl);

    cudaFuncSetAttribute(gemm_tc<false, false, true,  false, true>,
                         cudaFuncAttributeMaxDynamicSharedMemorySize, SMEM_BYTES);
    cudaFuncSetAttribute(gemm_tc<true,  false, true,  false, false>,
                         cudaFuncAttributeMaxDynamicSharedMemorySize, SMEM_BYTES);
    cudaFuncSetAttribute(gemm_tc<false, true,  false, true,  false>,
                         cudaFuncAttributeMaxDynamicSharedMemorySize, SMEM_BYTES);

    const int M = NTOK;
    const int MB = (M + BM - 1) / BM;   // 431

    // 0) Index/mask canonicalization
    detect_kernel<<<1, 256>>>(bidx, mask);
    convert_kernel<<<256, 256>>>(bidx, graph, mask);

    // 0b) One batched split-bf16 conversion (mq + 6 weights)
    {
        CvtBatch b;
        b.src[0] = mq; b.H[0] = mqh;          b.L[0] = mql;          b.n[0] = NTOK * EE;
        b.src[1] = Wq; b.H[1] = wh + WOFF_Q;  b.L[1] = wl + WOFF_Q;  b.n[1] = EE * EE;
        b.src[2] = Wk; b.H[2] = wh + WOFF_K;  b.L[2] = wl + WOFF_K;  b.n[2] = EE * EE;
        b.src[3] = Wv; b.H[3] = wh + WOFF_V;  b.L[3] = wl + WOFF_V;  b.n[3] = EE * EE;
        b.src[4] = Wo; b.H[4] = wh + WOFF_O;  b.L[4] = wl + WOFF_O;  b.n[4] = EE * EE;
        b.src[5] = W1; b.H[5] = wh + WOFF_1;  b.L[5] = wl + WOFF_1;  b.n[5] = FF * EE;
        b.src[6] = W2; b.H[6] = wh + WOFF_2;  b.L[6] = wl + WOFF_2;  b.n[6] = EE * FF;
        dim3 grid(128, 7);
        cvt_split_all<<<grid, 256>>>(b);
    }

    // 1) Fused Q/K/V projections: Q -> fp32 g_q, K/V -> bf16 g_kv
    {
        dim3 grid(MB, 2, 3);
        gemm_tc<false, false, true, false, true><<<grid, 256, SMEM_BYTES>>>(
            mqh, mql, wh, wl, 65536, bq, bk, bv,
            q, nullptr, nullptr, kvb, nullptr, M, EE, EE);
    }

    // 2) Attention (bf16 KV gather) -> split-bf16 o
    attn_kernel<<<M, 256>>>(q, kvb, oh, ol);

    // 3) Wo projection + residual(mq) -> x fp32; LN1 + split-bf16 x
    {
        dim3 grid(MB, 2, 1);
        gemm_tc<true, false, true, false, false><<<grid, 256, SMEM_BYTES>>>(
            oh, ol, wh + WOFF_O, wl + WOFF_O, 0, bo, bo, bo,
            x, nullptr, nullptr, nullptr, mq, M, EE, EE);
        ln_kernel<true><<<(M + 7) / 8, 256>>>(x, ln1g, ln1b, xh, xl, M);
    }

    // 4) FFN1 + GELU -> split-bf16 h only
    {
        dim3 grid(MB, 8, 1);
        gemm_tc<false, true, false, true, false><<<grid, 256, SMEM_BYTES>>>(
            xh, xl, wh + WOFF_1, wl + WOFF_1, 0, b1, b1, b1,
            nullptr, hh, hl, nullptr, nullptr, M, EE, FF);
    }

    // 5) FFN2 + residual(x) -> out fp32; LN2 in-place
    {
        dim3 grid(MB, 2, 1);
        gemm_tc<true, false, true, false, false><<<grid, 256, SMEM_BYTES>>>(
            hh, hl, wh + WOFF_2, wl + WOFF_2, 0, b2, b2, b2,
            out, nullptr, nullptr, nullptr, x, M, FF, EE);
        ln_kernel<false><<<(M + 7) / 8, 256>>>(out, ln2g, ln2b, nullptr, nullptr, M);
    }
}

// round 15
// speedup vs baseline: 1.2136x; 1.1763x over previous
#include <cuda_runtime.h>
#include <cuda_bf16.h>
#include <math.h>
#include <stdint.h>

// Problem constants
#define QM 8
#define VV 6890
#define KN 16
#define EE 256
#define HH 8
#define DD 32
#define NTOK (QM * VV)          // 55120
#define FF (4 * EE)             // 1024

// GEMM tiling: 3-stage pipeline, BK=32, XOR-swizzled 64B rows (no padding)
#define BM 128
#define BN 128
#define BK 32
#define PLANE_B 8192            // bytes per plane: 128 rows x 64 B
#define STAGE_BYTES (4 * PLANE_B)   // 32768 B (Ah,Al,Bh,Bl)
#define NSTAGE 3
#define SMEM_BYTES (NSTAGE * STAGE_BYTES)  // 98304 B

// Weight pack offsets (elements) in g_wh / g_wl
#define WOFF_Q  0
#define WOFF_K  65536
#define WOFF_V  131072
#define WOFF_O  196608
#define WOFF_1  262144
#define WOFF_2  524288
#define WTOTAL  786432

// Scratch (static device globals; no runtime allocation)
__device__ float g_q[(size_t)NTOK * EE];           // fp32 Q (attn input)
__device__ __nv_bfloat16 g_kv[(size_t)NTOK * 512]; // bf16 K|V (attn gather)
__device__ float g_x[(size_t)NTOK * EE];           // post-LN1 x fp32
__device__ __nv_bfloat16 g_mqh[(size_t)NTOK * EE], g_mql[(size_t)NTOK * EE];
__device__ __nv_bfloat16 g_oh [(size_t)NTOK * EE], g_ol [(size_t)NTOK * EE];
__device__ __nv_bfloat16 g_xh [(size_t)NTOK * EE], g_xl [(size_t)NTOK * EE];
__device__ __nv_bfloat16 g_hh [(size_t)NTOK * FF], g_hl [(size_t)NTOK * FF];
__device__ __nv_bfloat16 g_wh[WTOTAL], g_wl[WTOTAL];

__device__ int g_idx64;
__device__ int g_mask32;
__device__ int g_cidx[(size_t)NTOK * KN];
__device__ unsigned char g_cmask[(size_t)NTOK * KN];

// ---------------------------------------------------------------------------
// Dtype detection + canonicalization
// ---------------------------------------------------------------------------
__global__ void detect_kernel(const void* bidx, const void* mask)
{
    __shared__ int s_is64, s_m32;
    if (threadIdx.x == 0) { s_is64 = 1; s_m32 = 1; }
    __syncthreads();

    const unsigned long long* b64 = (const unsigned long long*)bidx;
    for (int i = threadIdx.x; i < 1024; i += blockDim.x)
        if (b64[i] >= (1ull << 32)) atomicExch(&s_is64, 0);

    const unsigned int* m32 = (const unsigned int*)mask;
    for (int i = threadIdx.x; i < 1024; i += blockDim.x)
        if (m32[i] > 1u) atomicExch(&s_m32, 0);

    __syncthreads();
    if (threadIdx.x == 0) { g_idx64 = s_is64; g_mask32 = s_m32; }
}

__global__ void convert_kernel(const void* bidx, const void* graph, const void* mask)
{
    const int is64 = g_idx64;
    const int m32  = g_mask32;
    const int total = NTOK * KN;
    for (int i = blockIdx.x * blockDim.x + threadIdx.x; i < total;
         i += gridDim.x * blockDim.x) {
        int b, g;
        if (is64) {
            b = (int)((const long long*)bidx)[i];
            g = (int)((const long long*)graph)[i];
        } else {
            b = ((const int*)bidx)[i];
            g = ((const int*)graph)[i];
        }
        g_cidx[i] = b * VV + g;
        g_cmask[i] = m32 ? (unsigned char)(((const int*)mask)[i] != 0)
                         : ((const unsigned char*)mask)[i];
    }
}

// ---------------------------------------------------------------------------
// fp32 -> split bf16
// ---------------------------------------------------------------------------
__device__ __forceinline__ void split_bf16(float x, __nv_bfloat16& h, __nv_bfloat16& l) {
    h = __float2bfloat16(x);
    l = __float2bfloat16(x - __bfloat162float(h));
}

struct CvtBatch {
    const float* src[7];
    __nv_bfloat16* H[7];
    __nv_bfloat16* L[7];
    int n[7];
};

__global__ void cvt_split_all(CvtBatch b)
{
    const int seg = blockIdx.y;
    const float* __restrict__ src = b.src[seg];
    __nv_bfloat16* __restrict__ H = b.H[seg];
    __nv_bfloat16* __restrict__ L = b.L[seg];
    const int n = b.n[seg];
    for (int i = (blockIdx.x * blockDim.x + threadIdx.x) * 4; i < n;
         i += gridDim.x * blockDim.x * 4) {
        float4 v = *(const float4*)(src + i);
        __nv_bfloat16 h0, h1, h2, h3, l0, l1, l2, l3;
        split_bf16(v.x, h0, l0); split_bf16(v.y, h1, l1);
        split_bf16(v.z, h2, l2); split_bf16(v.w, h3, l3);
        *(__nv_bfloat162*)(H + i)     = __nv_bfloat162(h0, h1);
        *(__nv_bfloat162*)(H + i + 2) = __nv_bfloat162(h2, h3);
        *(__nv_bfloat162*)(L + i)     = __nv_bfloat162(l0, l1);
        *(__nv_bfloat162*)(L + i + 2) = __nv_bfloat162(l2, l3);
    }
}

// ---------------------------------------------------------------------------
// MMA / async-copy helpers
// ---------------------------------------------------------------------------
__device__ __forceinline__ uint32_t smem_u32(const void* p) {
    return (uint32_t)__cvta_generic_to_shared(p);
}
__device__ __forceinline__ void ldsm_x4(uint32_t& r0, uint32_t& r1,
                                        uint32_t& r2, uint32_t& r3, uint32_t addr) {
    asm volatile("ldmatrix.sync.aligned.m8n8.x4.shared.b16 {%0,%1,%2,%3}, [%4];"
                 : "=r"(r0), "=r"(r1), "=r"(r2), "=r"(r3) : "r"(addr));
}
__device__ __forceinline__ void ldsm_x2(uint32_t& r0, uint32_t& r1, uint32_t addr) {
    asm volatile("ldmatrix.sync.aligned.m8n8.x2.shared.b16 {%0,%1}, [%2];"
                 : "=r"(r0), "=r"(r1) : "r"(addr));
}
__device__ __forceinline__ void mma_bf16(float* d, const uint32_t* a, const uint32_t* b) {
    asm volatile("mma.sync.aligned.m16n8k16.row.col.f32.bf16.bf16.f32 "
                 "{%0,%1,%2,%3}, {%4,%5,%6,%7}, {%8,%9}, {%0,%1,%2,%3};"
                 : "+f"(d[0]), "+f"(d[1]), "+f"(d[2]), "+f"(d[3])
                 : "r"(a[0]), "r"(a[1]), "r"(a[2]), "r"(a[3]), "r"(b[0]), "r"(b[1]));
}
__device__ __forceinline__ void cp_async16(uint32_t dst, const void* src, bool pred) {
    const int sz = pred ? 16 : 0;
    asm volatile("cp.async.cg.shared.global [%0], [%1], 16, %2;"
                 :: "r"(dst), "l"(src), "r"(sz));
}
__device__ __forceinline__ void cp_commit() { asm volatile("cp.async.commit_group;"); }
template<int N>
__device__ __forceinline__ void cp_wait() {
    asm volatile("cp.async.wait_group %0;" :: "n"(N));
}

__device__ __forceinline__ float gelu_exact(float x) {
    return 0.5f * x * (1.0f + erff(x * 0.7071067811865475f));
}

// XOR chunk swizzle: chunk ch (16B) of row r lives at (ch ^ ((r>>1)&3))
__device__ __forceinline__ uint32_t sw_off(int row, int ch) {
    return (uint32_t)(row * 64 + ((ch ^ ((row >> 1) & 3)) << 4));
}

// ---------------------------------------------------------------------------
// Split-bf16 tensor-core GEMM, 3-stage BK=32 cp.async pipeline,
// XOR-swizzled smem, 2 CTAs/SM.
// Outputs: fp32 C (OUTF32), split-bf16 Ch/Cl (OUTBF), or QKV mode (OUTKV).
// ---------------------------------------------------------------------------
template<bool HASRES, bool DOGELU, bool OUTF32, bool OUTBF, bool OUTKV>
__global__ void __launch_bounds__(256, 2)
gemm_tc(const __nv_bfloat16* __restrict__ Ah, const __nv_bfloat16* __restrict__ Al,
        const __nv_bfloat16* __restrict__ Whb, const __nv_bfloat16* __restrict__ Wlb,
        int wzstride,
        const float* __restrict__ ba, const float* __restrict__ bb,
        const float* __restrict__ bc,
        float* __restrict__ C, __nv_bfloat16* __restrict__ Ch,
        __nv_bfloat16* __restrict__ Cl, __nv_bfloat16* __restrict__ Ckv,
        const float* __restrict__ res,
        int M, int Kd, int ldc)
{
    extern __shared__ __nv_bfloat16 smem[];

    const int z = blockIdx.z;
    const __nv_bfloat16* Wh = Whb + (size_t)z * wzstride;
    const __nv_bfloat16* Wl = Wlb + (size_t)z * wzstride;
    const float* bias = (z == 0) ? ba : (z == 1) ? bb : bc;

    const int tid = threadIdx.x;
    const int lane = tid & 31;
    const int warp = tid >> 5;
    const int wm0 = (warp >> 2) * 64;
    const int wn0 = (warp & 3) * 32;

    const int row0 = blockIdx.x * BM;
    const int wcol0 = blockIdx.y * BN;

    float acc[4][4][4];
#pragma unroll
    for (int mi = 0; mi < 4; mi++)
#pragma unroll
        for (int ni = 0; ni < 4; ni++)
#pragma unroll
            for (int r = 0; r < 4; r++) acc[mi][ni][r] = 0.0f;

    const int nIter = Kd / BK;

    // Loader: per plane 512 chunks (128 rows x 4); 2 chunks per thread
    const int r0c = tid >> 2, c0c = tid & 3;
    const int r1c = (tid + 256) >> 2, c1c = c0c;
    const uint32_t sw0 = sw_off(r0c, c0c);
    const uint32_t sw1 = sw_off(r1c, c1c);
    const bool ap0 = (row0 + r0c) < M;
    const bool ap1 = (row0 + r1c) < M;

    const uint32_t smem_base = smem_u32(smem);

    // ldmatrix per-thread coords
    const int aRowL = wm0 + (lane & 15);     // + mi*16
    const int aChk  = (lane >> 4);           // +k2/8
    const int bRowL = wn0 + (lane & 7);      // + ni*8 (lanes 0-15 used)
    const int bChk  = ((lane & 15) >> 3);    // +k2/8

#define LOAD_STAGE(ST, KB)                                                     \
    do {                                                                       \
        const uint32_t st_ = smem_base + (ST) * STAGE_BYTES;                   \
        const size_t a0_ = (size_t)(row0 + r0c) * Kd + (KB) + c0c * 8;         \
        const size_t a1_ = (size_t)(row0 + r1c) * Kd + (KB) + c1c * 8;         \
        const size_t b0_ = (size_t)(wcol0 + r0c) * Kd + (KB) + c0c * 8;        \
        const size_t b1_ = (size_t)(wcol0 + r1c) * Kd + (KB) + c1c * 8;        \
        cp_async16(st_ + sw0,                 Ah + a0_, ap0);                  \
        cp_async16(st_ + sw1,                 Ah + a1_, ap1);                  \
        cp_async16(st_ + PLANE_B + sw0,       Al + a0_, ap0);                  \
        cp_async16(st_ + PLANE_B + sw1,       Al + a1_, ap1);                  \
        cp_async16(st_ + 2 * PLANE_B + sw0,   Wh + b0_, true);                 \
        cp_async16(st_ + 2 * PLANE_B + sw1,   Wh + b1_, true);                 \
        cp_async16(st_ + 3 * PLANE_B + sw0,   Wl + b0_, true);                 \
        cp_async16(st_ + 3 * PLANE_B + sw1,   Wl + b1_, true);                 \
        cp_commit();                                                           \
    } while (0)

    // ---- preload stages 0,1 ----
    LOAD_STAGE(0, 0);
    if (1 < nIter) { LOAD_STAGE(1, BK); } else { cp_commit(); }

    int cur = 0;
    for (int it = 0; it < nIter; it++) {
        if (it + 1 < nIter) cp_wait<1>(); else cp_wait<0>();
        __syncthreads();   // stage cur ready; compute(it-1) done on all threads

        if (it + 2 < nIter) {
            int ns = cur + 2; if (ns >= NSTAGE) ns -= NSTAGE;
            LOAD_STAGE(ns, (it + 2) * BK);
        }

        const uint32_t st = smem_base + cur * STAGE_BYTES;
#pragma unroll
        for (int k2 = 0; k2 < BK; k2 += 16) {
            const int kc = k2 >> 3;  // chunk base 0 or 2
            uint32_t ahf[4][4], alf[4][4], bhf[4][2], blf[4][2];
#pragma unroll
            for (int mi = 0; mi < 4; mi++) {
                const uint32_t off = sw_off(aRowL + mi * 16, kc + aChk);
                ldsm_x4(ahf[mi][0], ahf[mi][1], ahf[mi][2], ahf[mi][3], st + off);
                ldsm_x4(alf[mi][0], alf[mi][1], alf[mi][2], alf[mi][3],
                        st + PLANE_B + off);
            }
#pragma unroll
            for (int ni = 0; ni < 4; ni++) {
                const uint32_t off = sw_off(bRowL + ni * 8, kc + bChk);
                ldsm_x2(bhf[ni][0], bhf[ni][1], st + 2 * PLANE_B + off);
                ldsm_x2(blf[ni][0], blf[ni][1], st + 3 * PLANE_B + off);
            }
#pragma unroll
            for (int mi = 0; mi < 4; mi++)
#pragma unroll
                for (int ni = 0; ni < 4; ni++) {
                    mma_bf16(acc[mi][ni], ahf[mi], bhf[ni]);
                    mma_bf16(acc[mi][ni], ahf[mi], blf[ni]);
                    mma_bf16(acc[mi][ni], alf[mi], bhf[ni]);
                }
        }

        cur++; if (cur >= NSTAGE) cur = 0;
    }
#undef LOAD_STAGE

    // ---- epilogue ----
#pragma unroll
    for (int mi = 0; mi < 4; mi++) {
#pragma unroll
        for (int ni = 0; ni < 4; ni++) {
            const int rA = row0 + wm0 + mi * 16 + (lane >> 2);
            const int cw = wcol0 + wn0 + ni * 8 + 2 * (lane & 3);  // weight col
            const float b0 = bias[cw], b1 = bias[cw + 1];
#pragma unroll
            for (int half = 0; half < 2; half++) {
                const int r = rA + half * 8;
                if (r >= M) continue;
                float v0 = acc[mi][ni][half * 2 + 0] + b0;
                float v1 = acc[mi][ni][half * 2 + 1] + b1;
                if (HASRES) {
                    v0 += res[(size_t)r * ldc + cw];
                    v1 += res[(size_t)r * ldc + cw + 1];
                }
                if (DOGELU) { v0 = gelu_exact(v0); v1 = gelu_exact(v1); }
                if (OUTKV) {
                    if (z == 0) {
                        *(float2*)(C + (size_t)r * ldc + cw) = make_float2(v0, v1);
                    } else {
                        const int kcol = (z - 1) * 256 + cw;
                        *(__nv_bfloat162*)(Ckv + (size_t)r * 512 + kcol) =
                            __nv_bfloat162(__float2bfloat16(v0), __float2bfloat16(v1));
                    }
                } else {
                    if (OUTF32)
                        *(float2*)(C + (size_t)r * ldc + cw) = make_float2(v0, v1);
                    if (OUTBF) {
                        __nv_bfloat16 h0, h1, l0, l1;
                        split_bf16(v0, h0, l0); split_bf16(v1, h1, l1);
                        *(__nv_bfloat162*)(Ch + (size_t)r * ldc + cw) = __nv_bfloat162(h0, h1);
                        *(__nv_bfloat162*)(Cl + (size_t)r * ldc + cw) = __nv_bfloat162(l0, l1);
                    }
                }
            }
        }
    }
}

// ---------------------------------------------------------------------------
// Attention: one block per token (8 warps = 8 heads). Q fp32, K/V bf16 gather.
// ---------------------------------------------------------------------------
__global__ void __launch_bounds__(256)
attn_kernel(const float* __restrict__ q, const __nv_bfloat16* __restrict__ kv,
            __nv_bfloat16* __restrict__ oh, __nv_bfloat16* __restrict__ ol)
{
    const int n = blockIdx.x;
    __shared__ int s_m[KN];
    __shared__ unsigned char s_mask[KN];

    const int tid = threadIdx.x;
    if (tid < KN) {
        s_m[tid] = g_cidx[(size_t)n * KN + tid];
        s_mask[tid] = g_cmask[(size_t)n * KN + tid];
    }
    __syncthreads();

    const int h = tid >> 5;
    const int lane = tid & 31;
    const int hofs = h * DD + lane;

    const float qv = q[(size_t)n * EE + hofs];

    float sc[KN];
#pragma unroll
    for (int k = 0; k < KN; k++) {
        float p = qv * __bfloat162float(kv[(size_t)s_m[k] * 512 + hofs]);
        p += __shfl_xor_sync(0xffffffffu, p, 16);
        p += __shfl_xor_sync(0xffffffffu, p, 8);
        p += __shfl_xor_sync(0xffffffffu, p, 4);
        p += __shfl_xor_sync(0xffffffffu, p, 2);
        p += __shfl_xor_sync(0xffffffffu, p, 1);
        sc[k] = p;
    }

    const float NEGINF = __int_as_float(0xff800000);
    float mx = NEGINF;
#pragma unroll
    for (int k = 0; k < KN; k++) {
        sc[k] = s_mask[k] ? NEGINF : sc[k] * 0.1767766952966369f;
        mx = fmaxf(mx, sc[k]);
    }
    float sum = 0.0f;
#pragma unroll
    for (int k = 0; k < KN; k++) {
        sc[k] = __expf(sc[k] - mx);
        sum += sc[k];
    }
    const float inv = 1.0f / sum;

    float accv = 0.0f;
#pragma unroll
    for (int k = 0; k < KN; k++)
        accv = fmaf(sc[k], __bfloat162float(kv[(size_t)s_m[k] * 512 + 256 + hofs]),
                    accv);

    const float v = accv * inv;
    __nv_bfloat16 hh, ll;
    split_bf16(v, hh, ll);
    oh[(size_t)n * EE + hofs] = hh;
    ol[(size_t)n * EE + hofs] = ll;
}

// ---------------------------------------------------------------------------
// LayerNorm over E=256, warp per row, in-place fp32; optional split-bf16 out.
// ---------------------------------------------------------------------------
template<bool WRITEBF>
__global__ void __launch_bounds__(256)
ln_kernel(float* __restrict__ X, const float* __restrict__ gamma,
          const float* __restrict__ beta,
          __nv_bfloat16* __restrict__ Xh, __nv_bfloat16* __restrict__ Xl, int rows)
{
    const int row = blockIdx.x * 8 + (threadIdx.x >> 5);
    if (row >= rows) return;
    const int lane = threadIdx.x & 31;
    float* xr = X + (size_t)row * EE;

    float v[8];
    float s = 0.0f;
#pragma unroll
    for (int i = 0; i < 8; i++) {
        v[i] = xr[lane + i * 32];
        s += v[i];
    }
#pragma unroll
    for (int d = 16; d > 0; d >>= 1) s += __shfl_xor_sync(0xffffffffu, s, d);
    const float mean = s * (1.0f / 256.0f);

    float var = 0.0f;
#pragma unroll
    for (int i = 0; i < 8; i++) {
        const float d = v[i] - mean;
        var = fmaf(d, d, var);
    }
#pragma unroll
    for (int d = 16; d > 0; d >>= 1) var += __shfl_xor_sync(0xffffffffu, var, d);
    const float rstd = rsqrtf(var * (1.0f / 256.0f) + 1e-5f);

#pragma unroll
    for (int i = 0; i < 8; i++) {
        const int c = lane + i * 32;
        const float y = (v[i] - mean) * rstd * gamma[c] + beta[c];
        xr[c] = y;
        if (WRITEBF) {
            __nv_bfloat16 h, l;
            split_bf16(y, h, l);
            Xh[(size_t)row * EE + c] = h;
            Xl[(size_t)row * EE + c] = l;
        }
    }
}

// ---------------------------------------------------------------------------
extern "C" void kernel_launch(void* const* d_in, const int* in_sizes, int n_in,
                              void* d_out, int out_size)
{
    const float* mq    = (const float*)d_in[0];
    const float* Wq    = (const float*)d_in[1];
    const float* bq    = (const float*)d_in[2];
    const float* Wk    = (const float*)d_in[3];
    const float* bk    = (const float*)d_in[4];
    const float* Wv    = (const float*)d_in[5];
    const float* bv    = (const float*)d_in[6];
    const float* Wo    = (const float*)d_in[7];
    const float* bo    = (const float*)d_in[8];
    const float* ln1g  = (const float*)d_in[9];
    const float* ln1b  = (const float*)d_in[10];
    const float* W1    = (const float*)d_in[11];
    const float* b1    = (const float*)d_in[12];
    const float* W2    = (const float*)d_in[13];
    const float* b2    = (const float*)d_in[14];
    const float* ln2g  = (const float*)d_in[15];
    const float* ln2b  = (const float*)d_in[16];
    const void*  bidx  = d_in[17];
    const void*  graph = d_in[18];
    const void*  mask  = d_in[19];

    float* out = (float*)d_out;

    float* q;   cudaGetSymbolAddress((void**)&q,   g_q);
    float* x;   cudaGetSymbolAddress((void**)&x,   g_x);
    __nv_bfloat16 *kvb, *mqh, *mql, *oh, *ol, *xh, *xl, *hh, *hl, *wh, *wl;
    cudaGetSymbolAddress((void**)&kvb, g_kv);
    cudaGetSymbolAddress((void**)&mqh, g_mqh);
    cudaGetSymbolAddress((void**)&mql, g_mql);
    cudaGetSymbolAddress((void**)&oh,  g_oh);
    cudaGetSymbolAddress((void**)&ol,  g_ol);
    cudaGetSymbolAddress((void**)&xh,  g_xh);
    cudaGetSymbolAddress((void**)&xl,  g_xl);
    cudaGetSymbolAddress((void**)&hh,  g_hh);
    cudaGetSymbolAddress((void**)&hl,  g_hl);
    cudaGetSymbolAddress((void**)&wh,  g_wh);
    cudaGetSymbolAddress((void**)&wl,  g_wl);

    cudaFuncSetAttribute(gemm_tc<false, false, true,  false, true>,
                         cudaFuncAttributeMaxDynamicSharedMemorySize, SMEM_BYTES);
    cudaFuncSetAttribute(gemm_tc<true,  false, true,  false, false>,
                         cudaFuncAttributeMaxDynamicSharedMemorySize, SMEM_BYTES);
    cudaFuncSetAttribute(gemm_tc<false, true,  false, true,  false>,
                         cudaFuncAttributeMaxDynamicSharedMemorySize, SMEM_BYTES);

    const int M = NTOK;
    const int MB = (M + BM - 1) / BM;   // 431

    // 0) Index/mask canonicalization
    detect_kernel<<<1, 256>>>(bidx, mask);
    convert_kernel<<<256, 256>>>(bidx, graph, mask);

    // 0b) One batched split-bf16 conversion (mq + 6 weights)
    {
        CvtBatch b;
        b.src[0] = mq; b.H[0] = mqh;          b.L[0] = mql;          b.n[0] = NTOK * EE;
        b.src[1] = Wq; b.H[1] = wh + WOFF_Q;  b.L[1] = wl + WOFF_Q;  b.n[1] = EE * EE;
        b.src[2] = Wk; b.H[2] = wh + WOFF_K;  b.L[2] = wl + WOFF_K;  b.n[2] = EE * EE;
        b.src[3] = Wv; b.H[3] = wh + WOFF_V;  b.L[3] = wl + WOFF_V;  b.n[3] = EE * EE;
        b.src[4] = Wo; b.H[4] = wh + WOFF_O;  b.L[4] = wl + WOFF_O;  b.n[4] = EE * EE;
        b.src[5] = W1; b.H[5] = wh + WOFF_1;  b.L[5] = wl + WOFF_1;  b.n[5] = FF * EE;
        b.src[6] = W2; b.H[6] = wh + WOFF_2;  b.L[6] = wl + WOFF_2;  b.n[6] = EE * FF;
        dim3 grid(128, 7);
        cvt_split_all<<<grid, 256>>>(b);
    }

    // 1) Fused Q/K/V projections: Q -> fp32 g_q, K/V -> bf16 g_kv
    {
        dim3 grid(MB, 2, 3);
        gemm_tc<false, false, true, false, true><<<grid, 256, SMEM_BYTES>>>(
            mqh, mql, wh, wl, 65536, bq, bk, bv,
            q, nullptr, nullptr, kvb, nullptr, M, EE, EE);
    }

    // 2) Attention (bf16 KV gather) -> split-bf16 o
    attn_kernel<<<M, 256>>>(q, kvb, oh, ol);

    // 3) Wo projection + residual(mq) -> x fp32; LN1 + split-bf16 x
    {
        dim3 grid(MB, 2, 1);
        gemm_tc<true, false, true, false, false><<<grid, 256, SMEM_BYTES>>>(
            oh, ol, wh + WOFF_O, wl + WOFF_O, 0, bo, bo, bo,
            x, nullptr, nullptr, nullptr, mq, M, EE, EE);
        ln_kernel<true><<<(M + 7) / 8, 256>>>(x, ln1g, ln1b, xh, xl, M);
    }

    // 4) FFN1 + GELU -> split-bf16 h only
    {
        dim3 grid(MB, 8, 1);
        gemm_tc<false, true, false, true, false><<<grid, 256, SMEM_BYTES>>>(
            xh, xl, wh + WOFF_1, wl + WOFF_1, 0, b1, b1, b1,
            nullptr, hh, hl, nullptr, nullptr, M, EE, FF);
    }

    // 5) FFN2 + residual(x) -> out fp32; LN2 in-place
    {
        dim3 grid(MB, 2, 1);
        gemm_tc<true, false, true, false, false><<<grid, 256, SMEM_BYTES>>>(
            hh, hl, wh + WOFF_2, wl + WOFF_2, 0, b2, b2, b2,
            out, nullptr, nullptr, nullptr, x, M, FF, EE);
        ln_kernel<false><<<(M + 7) / 8, 256>>>(out, ln2g, ln2b, nullptr, nullptr, M);
    }
}

// round 16
// speedup vs baseline: 1.8603x; 1.5328x over previous
#include <cuda_runtime.h>
#include <cuda_bf16.h>
#include <math.h>
#include <stdint.h>

// Problem constants
#define QM 8
#define VV 6890
#define KN 16
#define EE 256
#define HH 8
#define DD 32
#define NTOK (QM * VV)          // 55120
#define FF (4 * EE)             // 1024

// GEMM tiling: single-product bf16, 3-stage pipeline, BK=64, 128B swizzled rows
#define BM 128
#define BN 128
#define BK 64
#define PLANE_B 16384           // bytes per plane: 128 rows x 128 B
#define STAGE_BYTES (2 * PLANE_B)   // 32768 B (A, B)
#define NSTAGE 3
#define SMEM_BYTES (NSTAGE * STAGE_BYTES)  // 98304 B

// Weight pack offsets (elements) in g_wb
#define WOFF_Q  0
#define WOFF_K  65536
#define WOFF_V  131072
#define WOFF_O  196608
#define WOFF_1  262144
#define WOFF_2  524288
#define WTOTAL  786432

// Scratch (static device globals; no runtime allocation)
__device__ float g_q[(size_t)NTOK * EE];           // fp32 Q (attn input)
__device__ __nv_bfloat16 g_kv[(size_t)NTOK * 512]; // bf16 K|V (attn gather)
__device__ float g_x[(size_t)NTOK * EE];           // post-LN1 x fp32 (residual)
__device__ __nv_bfloat16 g_mqb[(size_t)NTOK * EE]; // bf16 mq (QKV A operand)
__device__ __nv_bfloat16 g_ob [(size_t)NTOK * EE]; // bf16 o  (Wo A operand)
__device__ __nv_bfloat16 g_xb [(size_t)NTOK * EE]; // bf16 x  (FFN1 A operand)
__device__ __nv_bfloat16 g_hb [(size_t)NTOK * FF]; // bf16 h  (FFN2 A operand)
__device__ __nv_bfloat16 g_wb[WTOTAL];             // bf16 weights

__device__ int g_idx64;
__device__ int g_mask32;
__device__ int g_cidx[(size_t)NTOK * KN];
__device__ unsigned char g_cmask[(size_t)NTOK * KN];

// ---------------------------------------------------------------------------
// Dtype detection + canonicalization
// ---------------------------------------------------------------------------
__global__ void detect_kernel(const void* bidx, const void* mask)
{
    __shared__ int s_is64, s_m32;
    if (threadIdx.x == 0) { s_is64 = 1; s_m32 = 1; }
    __syncthreads();

    const unsigned long long* b64 = (const unsigned long long*)bidx;
    for (int i = threadIdx.x; i < 1024; i += blockDim.x)
        if (b64[i] >= (1ull << 32)) atomicExch(&s_is64, 0);

    const unsigned int* m32 = (const unsigned int*)mask;
    for (int i = threadIdx.x; i < 1024; i += blockDim.x)
        if (m32[i] > 1u) atomicExch(&s_m32, 0);

    __syncthreads();
    if (threadIdx.x == 0) { g_idx64 = s_is64; g_mask32 = s_m32; }
}

__global__ void convert_kernel(const void* bidx, const void* graph, const void* mask)
{
    const int is64 = g_idx64;
    const int m32  = g_mask32;
    const int total = NTOK * KN;
    for (int i = blockIdx.x * blockDim.x + threadIdx.x; i < total;
         i += gridDim.x * blockDim.x) {
        int b, g;
        if (is64) {
            b = (int)((const long long*)bidx)[i];
            g = (int)((const long long*)graph)[i];
        } else {
            b = ((const int*)bidx)[i];
            g = ((const int*)graph)[i];
        }
        g_cidx[i] = b * VV + g;
        g_cmask[i] = m32 ? (unsigned char)(((const int*)mask)[i] != 0)
                         : ((const unsigned char*)mask)[i];
    }
}

// ---------------------------------------------------------------------------
// fp32 -> bf16 batched convert (mq + 6 weights)
// ---------------------------------------------------------------------------
struct CvtBatch {
    const float* src[7];
    __nv_bfloat16* H[7];
    int n[7];
};

__global__ void cvt_bf16_all(CvtBatch b)
{
    const int seg = blockIdx.y;
    const float* __restrict__ src = b.src[seg];
    __nv_bfloat16* __restrict__ H = b.H[seg];
    const int n = b.n[seg];
    for (int i = (blockIdx.x * blockDim.x + threadIdx.x) * 4; i < n;
         i += gridDim.x * blockDim.x * 4) {
        float4 v = *(const float4*)(src + i);
        *(__nv_bfloat162*)(H + i) =
            __nv_bfloat162(__float2bfloat16(v.x), __float2bfloat16(v.y));
        *(__nv_bfloat162*)(H + i + 2) =
            __nv_bfloat162(__float2bfloat16(v.z), __float2bfloat16(v.w));
    }
}

// ---------------------------------------------------------------------------
// MMA / async-copy helpers
// ---------------------------------------------------------------------------
__device__ __forceinline__ uint32_t smem_u32(const void* p) {
    return (uint32_t)__cvta_generic_to_shared(p);
}
__device__ __forceinline__ void ldsm_x4(uint32_t& r0, uint32_t& r1,
                                        uint32_t& r2, uint32_t& r3, uint32_t addr) {
    asm volatile("ldmatrix.sync.aligned.m8n8.x4.shared.b16 {%0,%1,%2,%3}, [%4];"
                 : "=r"(r0), "=r"(r1), "=r"(r2), "=r"(r3) : "r"(addr));
}
__device__ __forceinline__ void ldsm_x2(uint32_t& r0, uint32_t& r1, uint32_t addr) {
    asm volatile("ldmatrix.sync.aligned.m8n8.x2.shared.b16 {%0,%1}, [%2];"
                 : "=r"(r0), "=r"(r1) : "r"(addr));
}
__device__ __forceinline__ void mma_bf16(float* d, const uint32_t* a, const uint32_t* b) {
    asm volatile("mma.sync.aligned.m16n8k16.row.col.f32.bf16.bf16.f32 "
                 "{%0,%1,%2,%3}, {%4,%5,%6,%7}, {%8,%9}, {%0,%1,%2,%3};"
                 : "+f"(d[0]), "+f"(d[1]), "+f"(d[2]), "+f"(d[3])
                 : "r"(a[0]), "r"(a[1]), "r"(a[2]), "r"(a[3]), "r"(b[0]), "r"(b[1]));
}
__device__ __forceinline__ void cp_async16(uint32_t dst, const void* src, bool pred) {
    const int sz = pred ? 16 : 0;
    asm volatile("cp.async.cg.shared.global [%0], [%1], 16, %2;"
                 :: "r"(dst), "l"(src), "r"(sz));
}
__device__ __forceinline__ void cp_commit() { asm volatile("cp.async.commit_group;"); }
template<int N>
__device__ __forceinline__ void cp_wait() {
    asm volatile("cp.async.wait_group %0;" :: "n"(N));
}

__device__ __forceinline__ float gelu_exact(float x) {
    return 0.5f * x * (1.0f + erff(x * 0.7071067811865475f));
}

// 128B-row XOR swizzle: chunk ch (16B, 0-7) of row r lives at (ch ^ (r & 7))
__device__ __forceinline__ uint32_t sw_off(int row, int ch) {
    return (uint32_t)(row * 128 + ((ch ^ (row & 7)) << 4));
}

// ---------------------------------------------------------------------------
// Single-product bf16 tensor-core GEMM, 3-stage BK=64 cp.async pipeline.
// Outputs: fp32 C (OUTF32), bf16 Cb (OUTBF), or QKV mode (OUTKV):
//   z==0 -> fp32 C (ldc), z==1/2 -> bf16 into Ckv[N][512] at (z-1)*256.
// ---------------------------------------------------------------------------
template<bool HASRES, bool DOGELU, bool OUTF32, bool OUTBF, bool OUTKV>
__global__ void __launch_bounds__(256, 2)
gemm_tc(const __nv_bfloat16* __restrict__ A,
        const __nv_bfloat16* __restrict__ Wb, int wzstride,
        const float* __restrict__ ba, const float* __restrict__ bb,
        const float* __restrict__ bc,
        float* __restrict__ C, __nv_bfloat16* __restrict__ Cb,
        __nv_bfloat16* __restrict__ Ckv,
        const float* __restrict__ res,
        int M, int Kd, int ldc)
{
    extern __shared__ __nv_bfloat16 smem[];

    const int z = blockIdx.z;
    const __nv_bfloat16* W = Wb + (size_t)z * wzstride;
    const float* bias = (z == 0) ? ba : (z == 1) ? bb : bc;

    const int tid = threadIdx.x;
    const int lane = tid & 31;
    const int warp = tid >> 5;
    const int wm0 = (warp >> 2) * 64;
    const int wn0 = (warp & 3) * 32;

    const int row0 = blockIdx.x * BM;
    const int wcol0 = blockIdx.y * BN;

    float acc[4][4][4];
#pragma unroll
    for (int mi = 0; mi < 4; mi++)
#pragma unroll
        for (int ni = 0; ni < 4; ni++)
#pragma unroll
            for (int r = 0; r < 4; r++) acc[mi][ni][r] = 0.0f;

    const int nIter = Kd / BK;

    const uint32_t smem_base = smem_u32(smem);

    // ldmatrix per-thread coords
    const int aRowL = wm0 + (lane & 15);     // + mi*16
    const int aChk  = (lane >> 4);           // + k2/8
    const int bRowL = wn0 + (lane & 7);      // + ni*8
    const int bChk  = ((lane & 15) >> 3);    // + k2/8

    // Loader: per plane 1024 chunks (128 rows x 8); 4 per thread per plane
#define LOAD_STAGE(ST, KB)                                                     \
    do {                                                                       \
        const uint32_t st_ = smem_base + (ST) * STAGE_BYTES;                   \
        _Pragma("unroll")                                                      \
        for (int i_ = 0; i_ < 4; i_++) {                                       \
            const int id_ = i_ * 256 + tid;                                    \
            const int row_ = id_ >> 3;                                         \
            const int ch_  = id_ & 7;                                          \
            const uint32_t sw_ = sw_off(row_, ch_);                            \
            const bool ap_ = (row0 + row_) < M;                                \
            const size_t ao_ = (size_t)(row0 + row_) * Kd + (KB) + ch_ * 8;    \
            const size_t bo_ = (size_t)(wcol0 + row_) * Kd + (KB) + ch_ * 8;   \
            cp_async16(st_ + sw_,           A + ao_, ap_);                     \
            cp_async16(st_ + PLANE_B + sw_, W + bo_, true);                    \
        }                                                                      \
        cp_commit();                                                           \
    } while (0)

    // ---- preload stages 0,1 ----
    LOAD_STAGE(0, 0);
    if (1 < nIter) { LOAD_STAGE(1, BK); } else { cp_commit(); }

    int cur = 0;
    for (int it = 0; it < nIter; it++) {
        if (it + 1 < nIter) cp_wait<1>(); else cp_wait<0>();
        __syncthreads();   // stage cur ready; compute(it-1) done on all threads

        if (it + 2 < nIter) {
            int ns = cur + 2; if (ns >= NSTAGE) ns -= NSTAGE;
            LOAD_STAGE(ns, (it + 2) * BK);
        }

        const uint32_t st = smem_base + cur * STAGE_BYTES;
#pragma unroll
        for (int k2 = 0; k2 < BK; k2 += 16) {
            const int kc = k2 >> 3;  // chunk base 0,2,4,6
            uint32_t af[4][4], bf[4][2];
#pragma unroll
            for (int mi = 0; mi < 4; mi++) {
                const uint32_t off = sw_off(aRowL + mi * 16, kc + aChk);
                ldsm_x4(af[mi][0], af[mi][1], af[mi][2], af[mi][3], st + off);
            }
#pragma unroll
            for (int ni = 0; ni < 4; ni++) {
                const uint32_t off = sw_off(bRowL + ni * 8, kc + bChk);
                ldsm_x2(bf[ni][0], bf[ni][1], st + PLANE_B + off);
            }
#pragma unroll
            for (int mi = 0; mi < 4; mi++)
#pragma unroll
                for (int ni = 0; ni < 4; ni++)
                    mma_bf16(acc[mi][ni], af[mi], bf[ni]);
        }

        cur++; if (cur >= NSTAGE) cur = 0;
    }
#undef LOAD_STAGE

    // ---- epilogue ----
#pragma unroll
    for (int mi = 0; mi < 4; mi++) {
#pragma unroll
        for (int ni = 0; ni < 4; ni++) {
            const int rA = row0 + wm0 + mi * 16 + (lane >> 2);
            const int cw = wcol0 + wn0 + ni * 8 + 2 * (lane & 3);  // weight col
            const float b0 = bias[cw], b1 = bias[cw + 1];
#pragma unroll
            for (int half = 0; half < 2; half++) {
                const int r = rA + half * 8;
                if (r >= M) continue;
                float v0 = acc[mi][ni][half * 2 + 0] + b0;
                float v1 = acc[mi][ni][half * 2 + 1] + b1;
                if (HASRES) {
                    v0 += res[(size_t)r * ldc + cw];
                    v1 += res[(size_t)r * ldc + cw + 1];
                }
                if (DOGELU) { v0 = gelu_exact(v0); v1 = gelu_exact(v1); }
                if (OUTKV) {
                    if (z == 0) {
                        *(float2*)(C + (size_t)r * ldc + cw) = make_float2(v0, v1);
                    } else {
                        const int kcol = (z - 1) * 256 + cw;
                        *(__nv_bfloat162*)(Ckv + (size_t)r * 512 + kcol) =
                            __nv_bfloat162(__float2bfloat16(v0), __float2bfloat16(v1));
                    }
                } else {
                    if (OUTF32)
                        *(float2*)(C + (size_t)r * ldc + cw) = make_float2(v0, v1);
                    if (OUTBF)
                        *(__nv_bfloat162*)(Cb + (size_t)r * ldc + cw) =
                            __nv_bfloat162(__float2bfloat16(v0), __float2bfloat16(v1));
                }
            }
        }
    }
}

// ---------------------------------------------------------------------------
// Attention: one block per token (8 warps = 8 heads). Q fp32, K/V bf16 gather.
// Writes bf16 o.
// ---------------------------------------------------------------------------
__global__ void __launch_bounds__(256)
attn_kernel(const float* __restrict__ q, const __nv_bfloat16* __restrict__ kv,
            __nv_bfloat16* __restrict__ ob)
{
    const int n = blockIdx.x;
    __shared__ int s_m[KN];
    __shared__ unsigned char s_mask[KN];

    const int tid = threadIdx.x;
    if (tid < KN) {
        s_m[tid] = g_cidx[(size_t)n * KN + tid];
        s_mask[tid] = g_cmask[(size_t)n * KN + tid];
    }
    __syncthreads();

    const int h = tid >> 5;
    const int lane = tid & 31;
    const int hofs = h * DD + lane;

    const float qv = q[(size_t)n * EE + hofs];

    float sc[KN];
#pragma unroll
    for (int k = 0; k < KN; k++) {
        float p = qv * __bfloat162float(kv[(size_t)s_m[k] * 512 + hofs]);
        p += __shfl_xor_sync(0xffffffffu, p, 16);
        p += __shfl_xor_sync(0xffffffffu, p, 8);
        p += __shfl_xor_sync(0xffffffffu, p, 4);
        p += __shfl_xor_sync(0xffffffffu, p, 2);
        p += __shfl_xor_sync(0xffffffffu, p, 1);
        sc[k] = p;
    }

    const float NEGINF = __int_as_float(0xff800000);
    float mx = NEGINF;
#pragma unroll
    for (int k = 0; k < KN; k++) {
        sc[k] = s_mask[k] ? NEGINF : sc[k] * 0.1767766952966369f;
        mx = fmaxf(mx, sc[k]);
    }
    float sum = 0.0f;
#pragma unroll
    for (int k = 0; k < KN; k++) {
        sc[k] = __expf(sc[k] - mx);
        sum += sc[k];
    }
    const float inv = 1.0f / sum;

    float accv = 0.0f;
#pragma unroll
    for (int k = 0; k < KN; k++)
        accv = fmaf(sc[k], __bfloat162float(kv[(size_t)s_m[k] * 512 + 256 + hofs]),
                    accv);

    ob[(size_t)n * EE + hofs] = __float2bfloat16(accv * inv);
}

// ---------------------------------------------------------------------------
// LayerNorm over E=256, warp per row, in-place fp32; optional bf16 out.
// ---------------------------------------------------------------------------
template<bool WRITEBF>
__global__ void __launch_bounds__(256)
ln_kernel(float* __restrict__ X, const float* __restrict__ gamma,
          const float* __restrict__ beta,
          __nv_bfloat16* __restrict__ Xb, int rows)
{
    const int row = blockIdx.x * 8 + (threadIdx.x >> 5);
    if (row >= rows) return;
    const int lane = threadIdx.x & 31;
    float* xr = X + (size_t)row * EE;

    float v[8];
    float s = 0.0f;
#pragma unroll
    for (int i = 0; i < 8; i++) {
        v[i] = xr[lane + i * 32];
        s += v[i];
    }
#pragma unroll
    for (int d = 16; d > 0; d >>= 1) s += __shfl_xor_sync(0xffffffffu, s, d);
    const float mean = s * (1.0f / 256.0f);

    float var = 0.0f;
#pragma unroll
    for (int i = 0; i < 8; i++) {
        const float d = v[i] - mean;
        var = fmaf(d, d, var);
    }
#pragma unroll
    for (int d = 16; d > 0; d >>= 1) var += __shfl_xor_sync(0xffffffffu, var, d);
    const float rstd = rsqrtf(var * (1.0f / 256.0f) + 1e-5f);

#pragma unroll
    for (int i = 0; i < 8; i++) {
        const int c = lane + i * 32;
        const float y = (v[i] - mean) * rstd * gamma[c] + beta[c];
        xr[c] = y;
        if (WRITEBF)
            Xb[(size_t)row * EE + c] = __float2bfloat16(y);
    }
}

// ---------------------------------------------------------------------------
extern "C" void kernel_launch(void* const* d_in, const int* in_sizes, int n_in,
                              void* d_out, int out_size)
{
    const float* mq    = (const float*)d_in[0];
    const float* Wq    = (const float*)d_in[1];
    const float* bq    = (const float*)d_in[2];
    const float* Wk    = (const float*)d_in[3];
    const float* bk    = (const float*)d_in[4];
    const float* Wv    = (const float*)d_in[5];
    const float* bv    = (const float*)d_in[6];
    const float* Wo    = (const float*)d_in[7];
    const float* bo    = (const float*)d_in[8];
    const float* ln1g  = (const float*)d_in[9];
    const float* ln1b  = (const float*)d_in[10];
    const float* W1    = (const float*)d_in[11];
    const float* b1    = (const float*)d_in[12];
    const float* W2    = (const float*)d_in[13];
    const float* b2    = (const float*)d_in[14];
    const float* ln2g  = (const float*)d_in[15];
    const float* ln2b  = (const float*)d_in[16];
    const void*  bidx  = d_in[17];
    const void*  graph = d_in[18];
    const void*  mask  = d_in[19];

    float* out = (float*)d_out;

    float* q;   cudaGetSymbolAddress((void**)&q,   g_q);
    float* x;   cudaGetSymbolAddress((void**)&x,   g_x);
    __nv_bfloat16 *kvb, *mqb, *ob, *xb, *hb, *wb;
    cudaGetSymbolAddress((void**)&kvb, g_kv);
    cudaGetSymbolAddress((void**)&mqb, g_mqb);
    cudaGetSymbolAddress((void**)&ob,  g_ob);
    cudaGetSymbolAddress((void**)&xb,  g_xb);
    cudaGetSymbolAddress((void**)&hb,  g_hb);
    cudaGetSymbolAddress((void**)&wb,  g_wb);

    cudaFuncSetAttribute(gemm_tc<false, false, true,  false, true>,
                         cudaFuncAttributeMaxDynamicSharedMemorySize, SMEM_BYTES);
    cudaFuncSetAttribute(gemm_tc<true,  false, true,  false, false>,
                         cudaFuncAttributeMaxDynamicSharedMemorySize, SMEM_BYTES);
    cudaFuncSetAttribute(gemm_tc<false, true,  false, true,  false>,
                         cudaFuncAttributeMaxDynamicSharedMemorySize, SMEM_BYTES);

    const int M = NTOK;
    const int MB = (M + BM - 1) / BM;   // 431

    // 0) Index/mask canonicalization
    detect_kernel<<<1, 256>>>(bidx, mask);
    convert_kernel<<<256, 256>>>(bidx, graph, mask);

    // 0b) One batched bf16 conversion (mq + 6 weights)
    {
        CvtBatch b;
        b.src[0] = mq; b.H[0] = mqb;          b.n[0] = NTOK * EE;
        b.src[1] = Wq; b.H[1] = wb + WOFF_Q;  b.n[1] = EE * EE;
        b.src[2] = Wk; b.H[2] = wb + WOFF_K;  b.n[2] = EE * EE;
        b.src[3] = Wv; b.H[3] = wb + WOFF_V;  b.n[3] = EE * EE;
        b.src[4] = Wo; b.H[4] = wb + WOFF_O;  b.n[4] = EE * EE;
        b.src[5] = W1; b.H[5] = wb + WOFF_1;  b.n[5] = FF * EE;
        b.src[6] = W2; b.H[6] = wb + WOFF_2;  b.n[6] = EE * FF;
        dim3 grid(128, 7);
        cvt_bf16_all<<<grid, 256>>>(b);
    }

    // 1) Fused Q/K/V projections: Q -> fp32 g_q, K/V -> bf16 g_kv
    {
        dim3 grid(MB, 2, 3);
        gemm_tc<false, false, true, false, true><<<grid, 256, SMEM_BYTES>>>(
            mqb, wb, 65536, bq, bk, bv,
            q, nullptr, kvb, nullptr, M, EE, EE);
    }

    // 2) Attention (bf16 KV gather) -> bf16 o
    attn_kernel<<<M, 256>>>(q, kvb, ob);

    // 3) Wo projection + residual(mq) -> x fp32; LN1 + bf16 x
    {
        dim3 grid(MB, 2, 1);
        gemm_tc<true, false, true, false, false><<<grid, 256, SMEM_BYTES>>>(
            ob, wb + WOFF_O, 0, bo, bo, bo,
            x, nullptr, nullptr, mq, M, EE, EE);
        ln_kernel<true><<<(M + 7) / 8, 256>>>(x, ln1g, ln1b, xb, M);
    }

    // 4) FFN1 + GELU -> bf16 h only
    {
        dim3 grid(MB, 8, 1);
        gemm_tc<false, true, false, true, false><<<grid, 256, SMEM_BYTES>>>(
            xb, wb + WOFF_1, 0, b1, b1, b1,
            nullptr, hb, nullptr, nullptr, M, EE, FF);
    }

    // 5) FFN2 + residual(x) -> out fp32; LN2 in-place
    {
        dim3 grid(MB, 2, 1);
        gemm_tc<true, false, true, false, false><<<grid, 256, SMEM_BYTES>>>(
            hb, wb + WOFF_2, 0, b2, b2, b2,
            out, nullptr, nullptr, x, M, FF, EE);
        ln_kernel<false><<<(M + 7) / 8, 256>>>(out, ln2g, ln2b, nullptr, M);
    }
}